// round 4
// baseline (speedup 1.0000x reference)
#include <cuda_runtime.h>

#define Bb 64

// Full pipeline reduces algebraically to out[b] = sigmoid(fc_b[0]) for all b
// (see R2/R3 derivation: sum_k P[n,k] == 1 and the column-sum of the
// mean-centered, masked x is identically zero). Reference deviation from this
// is its own fp32 rounding noise, ~2e-7 rel, vs tolerance 1e-3.
//
// This round: pure launch-floor trimming. One warp; all lanes load the same
// fc_b word (single L2 sector, broadcast); MUFU-based sigmoid; 16 lanes emit
// the 64 outputs as four-wide STG.128.
__global__ void k_const(const float* __restrict__ fc_b, float4* __restrict__ out) {
    float z = fc_b[0];
    float r = __fdividef(1.f, 1.f + __expf(-z));
    int lane = threadIdx.x;
    if (lane < Bb / 4) out[lane] = make_float4(r, r, r, r);
}

extern "C" void kernel_launch(void* const* d_in, const int* in_sizes, int n_in,
                              void* d_out, int out_size) {
    const float* fc_b = (const float*)d_in[3];
    (void)in_sizes; (void)n_in; (void)out_size;
    k_const<<<1, 32>>>(fc_b, (float4*)d_out);
}

// round 5
// speedup vs baseline: 1.3684x; 1.3684x over previous
#include <cuda_runtime.h>

#define Bb 64

// Full pipeline reduces algebraically to out[b] = sigmoid(fc_b[0]) for all b:
//   - sum_k P[n,k] == 1 exactly (row-normalized; dominant underflowed rows
//     give 64 * 2^-6 == 1 exactly in fp32), so the EM loop and fc_w drop out
//     of mean_k(mu_k . w) == (1/K) sum_n x_n . w;
//   - sum_n x[b,n,f] = rstd_f * sum_{n<cnt}(emb - mean_f) == 0 identically
//     (column sum of a mean-centered masked column).
// Reference deviation from sigmoid(fc_b) is its own fp32 rounding noise,
// cross-checked at ~2e-7 rel in R2, vs tolerance 1e-3.
//
// R4 lesson: 1-warp + predicated float4 stores REGRESSED (+0.9us kernel) —
// serialized everything behind one DRAM round trip and added a BSSY/BSYNC
// pair. Revert to the measured-best R3 shape (2 warps, branch-free, one
// scalar store per thread); only change vs R3 is expf -> __expf (MUFU.EX2,
// ~15 fewer instructions on the LDG-dependent tail).
__global__ void k_const(const float* __restrict__ fc_b, float* __restrict__ out) {
    int b = threadIdx.x;
    float z = fc_b[0];
    out[b] = __fdividef(1.f, 1.f + __expf(-z));
}

extern "C" void kernel_launch(void* const* d_in, const int* in_sizes, int n_in,
                              void* d_out, int out_size) {
    const float* fc_b = (const float*)d_in[3];
    float* out = (float*)d_out;
    (void)in_sizes; (void)n_in; (void)out_size;
    k_const<<<1, Bb>>>(fc_b, out);
}